// round 1
// baseline (speedup 1.0000x reference)
#include <cuda_runtime.h>

// Problem constants
#define Hs       49
#define G4       196            // 4*H
#define NLAYERS  7
#define IN0      7
#define NOUT     7
#define BATCH    1024
#define TT       512
#define KMAX     98             // H (recurrent) + H (input) for layers 1..6
#define K0       56             // H + IN0 for layer 0

// Kernel config
#define BBLK     8              // batch rows per block
#define NBLOCKS  128            // BATCH / BBLK
#define TPB      128            // blockDim = (64, 2)

#define SMEM_FLOATS (KMAX*G4 + G4 + 2*KMAX*BBLK)
#define SMEM_BYTES  (SMEM_FLOATS * 4)

// ---------------- device scratch (no runtime allocation allowed) ----------
__device__ float g_wp[NLAYERS][KMAX][G4];   // packed weights: [l][k][u*4 + gate]
__device__ float g_bp[NLAYERS][G4];         // packed bias:    [l][u*4 + gate]
__device__ float g_buf[2][TT][BATCH][Hs];   // inter-layer activations [T][B][H]

// ---------------- f32x2 helpers (Blackwell packed fp32) -------------------
static __device__ __forceinline__ unsigned long long pack2(float lo, float hi) {
    unsigned long long r;
    asm("mov.b64 %0, {%1,%2};" : "=l"(r) : "f"(lo), "f"(hi));
    return r;
}
static __device__ __forceinline__ void unpack2(unsigned long long v, float &lo, float &hi) {
    asm("mov.b64 {%0,%1}, %2;" : "=f"(lo), "=f"(hi) : "l"(v));
}
static __device__ __forceinline__ unsigned long long ffma2(unsigned long long a,
                                                           unsigned long long b,
                                                           unsigned long long c) {
    unsigned long long d;
    asm("fma.rn.f32x2 %0, %1, %2, %3;" : "=l"(d) : "l"(a), "l"(b), "l"(c));
    return d;
}

// Saturation-safe fast activations (MUFU.EX2 based, ~fp32 accurate)
static __device__ __forceinline__ float sigf(float x)  { return 1.f / (1.f + __expf(-x)); }
static __device__ __forceinline__ float tanhf2(float x){ return 1.f - 2.f / (1.f + __expf(2.f * x)); }

// ---------------- weight / bias packing -----------------------------------
// g_wp[l][k][u*4+j]: k<49 -> W_hh[l][j*49+u][k]; k>=49 -> input weights.
__global__ void pack_kernel(const float* __restrict__ W_ih0,
                            const float* __restrict__ W_ihr,
                            const float* __restrict__ W_hh,
                            const float* __restrict__ b_ih,
                            const float* __restrict__ b_hh) {
    int idx = blockIdx.x * blockDim.x + threadIdx.x;
    const int total = NLAYERS * KMAX * G4;
    if (idx >= total) return;
    int l   = idx / (KMAX * G4);
    int rem = idx % (KMAX * G4);
    int k   = rem / G4;
    int ug  = rem % G4;
    int u = ug >> 2, j = ug & 3;
    int row = j * Hs + u;               // torch gate order i,f,g,o
    float w = 0.f;
    if (k < Hs) {
        w = W_hh[(l * G4 + row) * Hs + k];
    } else {
        int kk = k - Hs;
        if (l == 0) {
            if (kk < IN0) w = W_ih0[row * IN0 + kk];
        } else {
            w = W_ihr[((l - 1) * G4 + row) * Hs + kk];
        }
    }
    g_wp[l][k][ug] = w;
    if (k == 0) g_bp[l][ug] = b_ih[l * G4 + row] + b_hh[l * G4 + row];
}

// ---------------- recurrent layer kernel ----------------------------------
// One block owns BBLK=8 batch rows for all T steps. blockDim=(64,2):
//   threadIdx.x = hidden unit u (0..48 active), threadIdx.y = batch group (4 rows).
// Each active thread computes all 4 gates of its unit for 4 batch rows via f32x2
// (batch-pair packed), then does the pointwise LSTM cell update locally.
__global__ __launch_bounds__(TPB, 1)
void lstm_layer_kernel(const float* __restrict__ xin, int layer, int ktot,
                       int din, long long tstride) {
    extern __shared__ float smem[];
    float* ws = smem;                       // [KMAX][G4]
    float* bs = ws + KMAX * G4;             // [G4]
    float* vv = bs + G4;                    // [2][KMAX][BBLK]  (h rows 0..48, x rows 49..)

    const int tid = threadIdx.y * 64 + threadIdx.x;
    const int u   = threadIdx.x;
    const int gy  = threadIdx.y;
    const int b0  = blockIdx.x * BBLK;
    const bool l0 = (layer == 0);

    const float* in = l0 ? xin : &g_buf[(layer - 1) & 1][0][0][0];
    float*      out = &g_buf[layer & 1][0][0][0];

    // Stage packed weights + bias in shared memory
    const float* wsrc = &g_wp[layer][0][0];
    for (int i = tid; i < ktot * G4; i += TPB) ws[i] = wsrc[i];
    for (int i = tid; i < G4; i += TPB)       bs[i] = g_bp[layer][i];
    for (int i = tid; i < 2 * KMAX * BBLK; i += TPB) vv[i] = 0.f;   // h(t=0)=0

    // Precompute per-thread input-prefetch offsets (t-invariant parts)
    const int npf = BBLK * din;
    long long pf_goff[4];
    int       pf_soff[4];
#pragma unroll
    for (int r = 0; r < 4; r++) {
        int e = tid + r * TPB;
        if (e < npf) {
            int b = e / din, k = e % din;
            pf_goff[r] = l0 ? ((long long)(b0 + b) * TT * IN0 + k)
                            : ((long long)(b0 + b) * Hs + k);
            pf_soff[r] = (Hs + k) * BBLK + b;
        } else {
            pf_goff[r] = -1;
            pf_soff[r] = 0;
        }
    }
    // Load x(t=0) into buffer 0
#pragma unroll
    for (int r = 0; r < 4; r++)
        if (pf_goff[r] >= 0) vv[pf_soff[r]] = in[pf_goff[r]];
    __syncthreads();

    // Per-thread recurrent cell state (4 batch rows) + packed bias
    float c[4] = {0.f, 0.f, 0.f, 0.f};
    unsigned long long bias2[4];
    if (u < Hs) {
#pragma unroll
        for (int j = 0; j < 4; j++) {
            float bj = bs[u * 4 + j];
            bias2[j] = pack2(bj, bj);
        }
    }

    for (int t = 0; t < TT; t++) {
        const int cur = t & 1, nxt = cur ^ 1;

        // Kick off global prefetch of layer input for t+1 (latency hidden by matvec)
        float pf[4];
        const bool do_pf = (t + 1 < TT);
        if (do_pf) {
#pragma unroll
            for (int r = 0; r < 4; r++)
                if (pf_goff[r] >= 0)
                    pf[r] = in[pf_goff[r] + (long long)(t + 1) * tstride];
        }

        if (u < Hs) {
            // gates[4][4 batch] = W * [h ; x] + b, f32x2 over batch pairs
            unsigned long long acc[4][2];
#pragma unroll
            for (int j = 0; j < 4; j++) { acc[j][0] = bias2[j]; acc[j][1] = bias2[j]; }

            const float* vrow = vv + cur * KMAX * BBLK + gy * 4;
            const float* wrow = ws + u * 4;
#pragma unroll 7
            for (int k = 0; k < ktot; k++) {
                float4 w  = *reinterpret_cast<const float4*>(wrow + k * G4);
                float4 hv = *reinterpret_cast<const float4*>(vrow + k * BBLK);
                unsigned long long h01 = pack2(hv.x, hv.y);
                unsigned long long h23 = pack2(hv.z, hv.w);
                unsigned long long w2;
                w2 = pack2(w.x, w.x); acc[0][0] = ffma2(w2, h01, acc[0][0]); acc[0][1] = ffma2(w2, h23, acc[0][1]);
                w2 = pack2(w.y, w.y); acc[1][0] = ffma2(w2, h01, acc[1][0]); acc[1][1] = ffma2(w2, h23, acc[1][1]);
                w2 = pack2(w.z, w.z); acc[2][0] = ffma2(w2, h01, acc[2][0]); acc[2][1] = ffma2(w2, h23, acc[2][1]);
                w2 = pack2(w.w, w.w); acc[3][0] = ffma2(w2, h01, acc[3][0]); acc[3][1] = ffma2(w2, h23, acc[3][1]);
            }

            float pre[4][4];
#pragma unroll
            for (int j = 0; j < 4; j++) {
                unpack2(acc[j][0], pre[j][0], pre[j][1]);
                unpack2(acc[j][1], pre[j][2], pre[j][3]);
            }

            float hh[4];
#pragma unroll
            for (int b = 0; b < 4; b++) {
                float ig = sigf(pre[0][b]);
                float fg = sigf(pre[1][b]);
                float gg = tanhf2(pre[2][b]);
                float og = sigf(pre[3][b]);
                c[b]  = fg * c[b] + ig * gg;
                hh[b] = og * tanhf2(c[b]);
            }

            // h -> next smem buffer (transposed layout [k=u][b]) + global layer output
            float4 h4 = make_float4(hh[0], hh[1], hh[2], hh[3]);
            *reinterpret_cast<float4*>(vv + (nxt * KMAX + u) * BBLK + gy * 4) = h4;
#pragma unroll
            for (int b = 0; b < 4; b++)
                out[(long long)t * BATCH * Hs + (b0 + gy * 4 + b) * Hs + u] = hh[b];
        }

        // Commit prefetched x(t+1) into next buffer
        if (do_pf) {
#pragma unroll
            for (int r = 0; r < 4; r++)
                if (pf_goff[r] >= 0) vv[nxt * KMAX * BBLK + pf_soff[r]] = pf[r];
        }
        __syncthreads();
    }
}

// ---------------- final FC: out[b][t][o] = h7[t][b][:] @ fc_w[o][:] + fc_b --
#define FCB 128
__global__ void fc_kernel(const float* __restrict__ fc_w,
                          const float* __restrict__ fc_b,
                          float* __restrict__ outp) {
    __shared__ float sh[FCB * Hs];
    __shared__ float sw[NOUT * Hs + NOUT];
    const float* hbuf = &g_buf[(NLAYERS - 1) & 1][0][0][0];
    int t   = blockIdx.x;
    int bc  = blockIdx.y;
    int tid = threadIdx.x;

    for (int i = tid; i < FCB * Hs; i += FCB)
        sh[i] = hbuf[(long long)t * BATCH * Hs + (long long)bc * FCB * Hs + i];
    for (int i = tid; i < NOUT * Hs; i += FCB) sw[i] = fc_w[i];
    if (tid < NOUT) sw[NOUT * Hs + tid] = fc_b[tid];
    __syncthreads();

    int b = bc * FCB + tid;
    float o[NOUT];
#pragma unroll
    for (int j = 0; j < NOUT; j++) o[j] = sw[NOUT * Hs + j];
#pragma unroll
    for (int k = 0; k < Hs; k++) {
        float h = sh[tid * Hs + k];
#pragma unroll
        for (int j = 0; j < NOUT; j++) o[j] += h * sw[j * Hs + k];
    }
#pragma unroll
    for (int j = 0; j < NOUT; j++)
        outp[(long long)b * TT * NOUT + t * NOUT + j] = o[j];
}

// ---------------- launcher -------------------------------------------------
extern "C" void kernel_launch(void* const* d_in, const int* in_sizes, int n_in,
                              void* d_out, int out_size) {
    const float* x     = (const float*)d_in[0];
    const float* W_ih0 = (const float*)d_in[1];
    const float* W_ihr = (const float*)d_in[2];
    const float* W_hh  = (const float*)d_in[3];
    const float* b_ih  = (const float*)d_in[4];
    const float* b_hh  = (const float*)d_in[5];
    const float* fc_w  = (const float*)d_in[6];
    const float* fc_b  = (const float*)d_in[7];
    float* outp = (float*)d_out;

    cudaFuncSetAttribute(lstm_layer_kernel,
                         cudaFuncAttributeMaxDynamicSharedMemorySize, SMEM_BYTES);

    const int total = NLAYERS * KMAX * G4;
    pack_kernel<<<(total + 255) / 256, 256>>>(W_ih0, W_ihr, W_hh, b_ih, b_hh);

    for (int l = 0; l < NLAYERS; l++) {
        int ktot = (l == 0) ? K0 : KMAX;
        int din  = (l == 0) ? IN0 : Hs;
        long long tstride = (l == 0) ? (long long)IN0 : (long long)BATCH * Hs;
        lstm_layer_kernel<<<NBLOCKS, dim3(64, 2), SMEM_BYTES>>>(x, l, ktot, din, tstride);
    }

    dim3 fcg(TT, BATCH / FCB);
    fc_kernel<<<fcg, FCB>>>(fc_w, fc_b, outp);
}